// round 9
// baseline (speedup 1.0000x reference)
#include <cuda_runtime.h>
#include <cuda_bf16.h>
#include <math.h>

#define T_ 512
#define H_ 1024
#define BH 65536
#define TBH ((size_t)T_*BH)
#define NBLK 128
#define NTHR 512
typedef unsigned long long ull;
typedef unsigned int u32;

__device__ float g_h0[2][BH];
__device__ float g_p0[8][BH];
__device__ float g_px[8][BH];
__device__ float g_p1[16][BH];
__device__ float g_b0[H_], g_b1[H_];
__device__ unsigned g_cnt = 0, g_ep = 0;

__device__ __forceinline__ void gbar(){
    __syncthreads();
    if (threadIdx.x == 0){
        volatile unsigned* ep = &g_ep;
        unsigned e = *ep;                  // read BEFORE arriving (monotonic epoch)
        __threadfence();
        if (atomicAdd(&g_cnt, 1u) == NBLK - 1u){
            g_cnt = 0; __threadfence(); atomicAdd(&g_ep, 1u);
        } else {
            while (*ep == e) __nanosleep(32);
        }
        __threadfence();
    }
    __syncthreads();
}

__device__ __forceinline__ u32 smaddr(const void* p){
    u32 a; asm("{ .reg .u64 t; cvta.to.shared.u64 t, %1; cvt.u32.u64 %0, t; }" : "=r"(a) : "l"(p));
    return a;
}

__device__ __forceinline__ void split4(float4 v, ull &hp, ull &lp){
    __nv_bfloat16 h0=__float2bfloat16_rn(v.x), h1=__float2bfloat16_rn(v.y),
                  h2=__float2bfloat16_rn(v.z), h3=__float2bfloat16_rn(v.w);
    __nv_bfloat16 l0=__float2bfloat16_rn(v.x-__bfloat162float(h0)),
                  l1=__float2bfloat16_rn(v.y-__bfloat162float(h1)),
                  l2=__float2bfloat16_rn(v.z-__bfloat162float(h2)),
                  l3=__float2bfloat16_rn(v.w-__bfloat162float(h3));
    hp = (ull)__bfloat16_as_ushort(h0) | ((ull)__bfloat16_as_ushort(h1)<<16)
       | ((ull)__bfloat16_as_ushort(h2)<<32) | ((ull)__bfloat16_as_ushort(h3)<<48);
    lp = (ull)__bfloat16_as_ushort(l0) | ((ull)__bfloat16_as_ushort(l1)<<16)
       | ((ull)__bfloat16_as_ushort(l2)<<32) | ((ull)__bfloat16_as_ushort(l3)<<48);
}

__device__ __forceinline__ void ldsm4(u32 &r0,u32 &r1,u32 &r2,u32 &r3, u32 a){
    asm volatile("ldmatrix.sync.aligned.m8n8.x4.shared.b16 {%0,%1,%2,%3}, [%4];"
                 : "=r"(r0),"=r"(r1),"=r"(r2),"=r"(r3) : "r"(a));
}
__device__ __forceinline__ void mma16816(float* d, u32 a0,u32 a1,u32 a2,u32 a3, u32 b0,u32 b1){
    asm volatile("mma.sync.aligned.m16n8k16.row.col.f32.bf16.bf16.f32 "
                 "{%0,%1,%2,%3}, {%4,%5,%6,%7}, {%8,%9}, {%0,%1,%2,%3};"
                 : "+f"(d[0]),"+f"(d[1]),"+f"(d[2]),"+f"(d[3])
                 : "r"(a0),"r"(a1),"r"(a2),"r"(a3),"r"(b0),"r"(b1));
}

// smem: W hi/lo 256x128 bf16 swizzled (64KB each), A hi/lo 64x128 bf16 (16KB each)
#define SMEM_BYTES (2*65536 + 2*16384)

__global__ void __launch_bounds__(NTHR, 1) k_rnn(
    const float* __restrict__ input, const float* __restrict__ h0_in,
    const float* __restrict__ Wih0, const float* __restrict__ bih0,
    const float* __restrict__ Whh0, const float* __restrict__ bhh0,
    const float* __restrict__ Wih1, const float* __restrict__ bih1,
    const float* __restrict__ Whh1, const float* __restrict__ bhh1,
    float* __restrict__ out)
{
    extern __shared__ char smch[];
    char* sWhi = smch;
    char* sWlo = smch + 65536;
    char* sAhi = smch + 131072;
    char* sAlo = smch + 147456;

    const int bid = blockIdx.x, t = threadIdx.x;
    const int l = t & 31, w = t >> 5;          // 16 warps

    // ---- task decode: 0..31 L0, 32..63 X0, 64..127 L1 ----
    int kind, j0, k0;
    const float* Wsrc; float* P;
    if (bid < 32){       kind = 0; j0 = (bid >> 3)*256; k0 = (bid & 7)*128; Wsrc = Whh0; P = g_p0[bid & 7]; }
    else if (bid < 64){  int x = bid - 32; kind = 1; j0 = (x >> 3)*256; k0 = (x & 7)*128; Wsrc = Wih0; P = g_px[x & 7]; }
    else {               int lt = bid - 64; int kc = lt & 15; int kg = kc*128; j0 = (lt >> 4)*256; P = g_p1[kc];
                         if (kg < 1024){ kind = 2; k0 = kg; Wsrc = Wih1; }
                         else          { kind = 3; k0 = kg - 1024; Wsrc = Whh1; } }

    // ---- stage W hi/lo ONCE (XOR-swizzled rows of 256B) ----
    for (int u = t; u < 256*32; u += NTHR){
        int j = u >> 5, kq = u & 31;
        float4 v = *(const float4*)&Wsrc[(size_t)(j0 + j)*1024 + k0 + 4*kq];
        ull hp, lp; split4(v, hp, lp);
        int off = j*256 + ((kq*8) ^ ((j & 7) << 4));
        *(ull*)(sWhi + off) = hp; *(ull*)(sWlo + off) = lp;
    }

    // ---- init biases + h0 seed ----
    const int gid = bid*NTHR + t, gs = NBLK*NTHR;
    for (int j = gid; j < H_; j += gs){ g_b0[j] = bih0[j] + bhh0[j]; g_b1[j] = bih1[j] + bhh1[j]; }
    for (int i = gid; i < BH; i += gs) g_h0[1][i] = h0_in[i];
    gbar();

    // per-lane ldmatrix geometry (all NON-trans; B is N x K row-major = .col operand)
    const int r   = l & 7;
    const u32 r16 = (u32)r << 4;
    const int halfm = (l >> 3) & 1;      // A: m-half | B: k-half
    const int kh    = l >> 4;            // A: k-half | B: n-half
    const u32 aWhi = smaddr(sWhi), aWlo = smaddr(sWlo);
    const u32 aAhi = smaddr(sAhi), aAlo = smaddr(sAlo);
    u32 aOff[4];
    #pragma unroll
    for (int mt = 0; mt < 4; ++mt) aOff[mt] = (u32)(mt*16 + halfm*8 + r) * 256;
    const u32 bOff = (u32)(w*16 + kh*8 + r) * 256;    // warp covers 16 cols
    const u32 aKl = (u32)kh << 4;        // A lane k-byte offset (k+8)
    const u32 bKl = (u32)halfm << 4;     // B lane k-byte offset (k+8)

    for (int s = 0; s <= T_; ++s){
        const float* h0p = g_h0[(s + 1) & 1];
        const bool act = (kind <= 1) ? (s < T_) : (s >= 1);

        if (act){
            const float* Asrc;
            if (kind == 0 || kind == 2) Asrc = h0p + k0;
            else if (kind == 1)         Asrc = input + (size_t)s*BH + k0;
            else                        Asrc = ((s == 1) ? (h0_in + BH) : (out + (size_t)(s-2)*BH)) + k0;

            // stage A hi/lo (64 rows x 128 k)
            for (int u = t; u < 64*32; u += NTHR){
                int rr = u >> 5, kq = u & 31;
                float4 v = *(const float4*)&Asrc[(size_t)rr*1024 + 4*kq];
                ull hp, lp; split4(v, hp, lp);
                int off = rr*256 + ((kq*8) ^ ((rr & 7) << 4));
                *(ull*)(sAhi + off) = hp; *(ull*)(sAlo + off) = lp;
            }
            __syncthreads();

            float acc[4][2][4];
            #pragma unroll
            for (int i = 0; i < 4; ++i)
                #pragma unroll
                for (int j = 0; j < 2; ++j)
                    #pragma unroll
                    for (int q = 0; q < 4; ++q) acc[i][j][q] = 0.f;

            #pragma unroll
            for (int pass = 0; pass < 3; ++pass){
                const u32 aB = (pass == 1) ? aAlo : aAhi;
                const u32 bB = (pass == 2) ? aWlo : aWhi;
                #pragma unroll
                for (int ks = 0; ks < 8; ++ks){
                    u32 a[4][4], b[4];
                    #pragma unroll
                    for (int mt = 0; mt < 4; ++mt)
                        ldsm4(a[mt][0], a[mt][1], a[mt][2], a[mt][3],
                              aB + aOff[mt] + (((u32)(ks*32) + aKl) ^ r16));
                    ldsm4(b[0], b[1], b[2], b[3],
                          bB + bOff + (((u32)(ks*32) + bKl) ^ r16));
                    #pragma unroll
                    for (int mt = 0; mt < 4; ++mt){
                        mma16816(acc[mt][0], a[mt][0],a[mt][1],a[mt][2],a[mt][3], b[0], b[1]);
                        mma16816(acc[mt][1], a[mt][0],a[mt][1],a[mt][2],a[mt][3], b[2], b[3]);
                    }
                }
            }

            // epilogue: d-frag -> partials (row-major, float2 stores)
            const int erow = l >> 2, ecol = (l & 3)*2;
            #pragma unroll
            for (int mt = 0; mt < 4; ++mt)
                #pragma unroll
                for (int nt = 0; nt < 2; ++nt){
                    const int row = mt*16 + erow;
                    const int col = j0 + w*16 + nt*8 + ecol;
                    *(float2*)&P[(size_t)row*1024 + col]      = make_float2(acc[mt][nt][0], acc[mt][nt][1]);
                    *(float2*)&P[(size_t)(row+8)*1024 + col]  = make_float2(acc[mt][nt][2], acc[mt][nt][3]);
                }
        }
        gbar();

        // ---- reduce + tanh ----
        for (int i = gid; i < 2*(BH/4); i += gs){
            if (i < BH/4){
                if (s < T_){
                    float4 v = *(const float4*)&g_b0[(i & 255)*4];
                    #pragma unroll
                    for (int p = 0; p < 8; ++p){
                        float4 a = *(const float4*)&g_p0[p][i*4];
                        float4 b = *(const float4*)&g_px[p][i*4];
                        v.x += a.x + b.x; v.y += a.y + b.y;
                        v.z += a.z + b.z; v.w += a.w + b.w;
                    }
                    *(float4*)&g_h0[s & 1][i*4] =
                        make_float4(tanhf(v.x), tanhf(v.y), tanhf(v.z), tanhf(v.w));
                }
            } else if (s >= 1){
                int e = i - BH/4;
                float4 v = *(const float4*)&g_b1[(e & 255)*4];
                #pragma unroll
                for (int p = 0; p < 16; ++p){
                    float4 a = *(const float4*)&g_p1[p][e*4];
                    v.x += a.x; v.y += a.y; v.z += a.z; v.w += a.w;
                }
                *(float4*)&out[(size_t)(s-1)*BH + e*4] =
                    make_float4(tanhf(v.x), tanhf(v.y), tanhf(v.z), tanhf(v.w));
            }
        }
        gbar();
    }

    for (int i = gid; i < BH; i += gs){
        out[TBH + i]      = g_h0[(T_ - 1) & 1][i];
        out[TBH + BH + i] = out[(size_t)(T_ - 1)*BH + i];
    }
}

extern "C" void kernel_launch(void* const* d_in, const int* in_sizes, int n_in,
                              void* d_out, int out_size)
{
    const float* input = (const float*)d_in[0];
    const float* h0in  = (const float*)d_in[1];
    const float* Wih0  = (const float*)d_in[2];
    const float* bih0  = (const float*)d_in[3];
    const float* Whh0  = (const float*)d_in[4];
    const float* bhh0  = (const float*)d_in[5];
    const float* Wih1  = (const float*)d_in[6];
    const float* bih1  = (const float*)d_in[7];
    const float* Whh1  = (const float*)d_in[8];
    const float* bhh1  = (const float*)d_in[9];
    float* out = (float*)d_out;

    cudaFuncSetAttribute(k_rnn, cudaFuncAttributeMaxDynamicSharedMemorySize, SMEM_BYTES);
    k_rnn<<<NBLK, NTHR, SMEM_BYTES>>>(input, h0in, Wih0, bih0, Whh0, bhh0,
                                      Wih1, bih1, Whh1, bhh1, out);
}

// round 12
// speedup vs baseline: 1.0662x; 1.0662x over previous
#include <cuda_runtime.h>
#include <cuda_bf16.h>
#include <math.h>

#define T_ 512
#define H_ 1024
#define BH 65536
#define TBH ((size_t)T_*BH)
#define NBLK 128
#define NTHR 256
typedef unsigned long long ull;
typedef unsigned int u32;

__device__ float g_h0[2][BH];
__device__ float g_p0[8][BH];
__device__ float g_px[8][BH];
__device__ float g_p1[16][BH];
__device__ float g_b0[H_], g_b1[H_];
__device__ u32 g_flags[NBLK];      // persistent, monotonically increasing across launches
__device__ u32 g_release;

// Flag/master grid barrier. All blocks arrive via independent flag stores;
// block 0 warp 0 polls all flags (4 per lane), then publishes release word.
// target = base + phase stays consistent across graph replays because flags
// persist and every launch executes the same number of barriers.
__device__ __forceinline__ void gbar(int bid, u32 &phase, u32 base){
    __syncthreads();
    ++phase;
    const u32 target = base + phase;
    if (threadIdx.x < 32){
        if (threadIdx.x == 0){
            __threadfence();                               // drain my writes (+IVALL)
            *((volatile u32*)&g_flags[bid]) = target;      // arrive
        }
        if (bid == 0){
            const int l = threadIdx.x;
            #pragma unroll
            for (int q = 0; q < NBLK/32; ++q)
                while (*((volatile u32*)&g_flags[l + 32*q]) < target) { }
            __syncwarp();
            if (l == 0){
                __threadfence();                           // order + IVALL for master
                *((volatile u32*)&g_release) = target;     // release
            }
        } else if (threadIdx.x == 0){
            while (*((volatile u32*)&g_release) < target) { }
            __threadfence();                               // IVALL: drop stale L1 lines
        }
    }
    __syncthreads();
}

__device__ __forceinline__ u32 smaddr(const void* p){
    u32 a; asm("{ .reg .u64 t; cvta.to.shared.u64 t, %1; cvt.u32.u64 %0, t; }" : "=r"(a) : "l"(p));
    return a;
}

__device__ __forceinline__ void split4(float4 v, ull &hp, ull &lp){
    __nv_bfloat16 h0=__float2bfloat16_rn(v.x), h1=__float2bfloat16_rn(v.y),
                  h2=__float2bfloat16_rn(v.z), h3=__float2bfloat16_rn(v.w);
    __nv_bfloat16 l0=__float2bfloat16_rn(v.x-__bfloat162float(h0)),
                  l1=__float2bfloat16_rn(v.y-__bfloat162float(h1)),
                  l2=__float2bfloat16_rn(v.z-__bfloat162float(h2)),
                  l3=__float2bfloat16_rn(v.w-__bfloat162float(h3));
    hp = (ull)__bfloat16_as_ushort(h0) | ((ull)__bfloat16_as_ushort(h1)<<16)
       | ((ull)__bfloat16_as_ushort(h2)<<32) | ((ull)__bfloat16_as_ushort(h3)<<48);
    lp = (ull)__bfloat16_as_ushort(l0) | ((ull)__bfloat16_as_ushort(l1)<<16)
       | ((ull)__bfloat16_as_ushort(l2)<<32) | ((ull)__bfloat16_as_ushort(l3)<<48);
}

__device__ __forceinline__ void ldsm4(u32 &r0,u32 &r1,u32 &r2,u32 &r3, u32 a){
    asm volatile("ldmatrix.sync.aligned.m8n8.x4.shared.b16 {%0,%1,%2,%3}, [%4];"
                 : "=r"(r0),"=r"(r1),"=r"(r2),"=r"(r3) : "r"(a));
}
__device__ __forceinline__ void mma16816(float* d, u32 a0,u32 a1,u32 a2,u32 a3, u32 b0,u32 b1){
    asm volatile("mma.sync.aligned.m16n8k16.row.col.f32.bf16.bf16.f32 "
                 "{%0,%1,%2,%3}, {%4,%5,%6,%7}, {%8,%9}, {%0,%1,%2,%3};"
                 : "+f"(d[0]),"+f"(d[1]),"+f"(d[2]),"+f"(d[3])
                 : "r"(a0),"r"(a1),"r"(a2),"r"(a3),"r"(b0),"r"(b1));
}

// smem: W hi/lo 256x128 bf16 swizzled (64KB each), A hi/lo 64x128 bf16 (16KB each)
#define SMEM_BYTES (2*65536 + 2*16384)

__global__ void __launch_bounds__(NTHR, 1) k_rnn(
    const float* __restrict__ input, const float* __restrict__ h0_in,
    const float* __restrict__ Wih0, const float* __restrict__ bih0,
    const float* __restrict__ Whh0, const float* __restrict__ bhh0,
    const float* __restrict__ Wih1, const float* __restrict__ bih1,
    const float* __restrict__ Whh1, const float* __restrict__ bhh1,
    float* __restrict__ out)
{
    extern __shared__ char smch[];
    char* sWhi = smch;
    char* sWlo = smch + 65536;
    char* sAhi = smch + 131072;
    char* sAlo = smch + 147456;

    const int bid = blockIdx.x, t = threadIdx.x;
    const int l = t & 31, w = t >> 5;

    // barrier epoch base (flags persist across launches; all equal at entry)
    const u32 ep_base = g_flags[bid];
    u32 phase = 0;

    // ---- task decode: 0..31 L0, 32..63 X0, 64..127 L1 ----
    int kind, j0, k0;
    const float* Wsrc; float* P;
    if (bid < 32){       kind = 0; j0 = (bid >> 3)*256; k0 = (bid & 7)*128; Wsrc = Whh0; P = g_p0[bid & 7]; }
    else if (bid < 64){  int x = bid - 32; kind = 1; j0 = (x >> 3)*256; k0 = (x & 7)*128; Wsrc = Wih0; P = g_px[x & 7]; }
    else {               int lt = bid - 64; int kc = lt & 15; int kg = kc*128; j0 = (lt >> 4)*256; P = g_p1[kc];
                         if (kg < 1024){ kind = 2; k0 = kg; Wsrc = Wih1; }
                         else          { kind = 3; k0 = kg - 1024; Wsrc = Whh1; } }

    // ---- stage W hi/lo ONCE (XOR-swizzled rows of 256B) ----
    for (int u = t; u < 256*32; u += NTHR){
        int j = u >> 5, kq = u & 31;
        float4 v = *(const float4*)&Wsrc[(size_t)(j0 + j)*1024 + k0 + 4*kq];
        ull hp, lp; split4(v, hp, lp);
        int off = j*256 + ((kq*8) ^ ((j & 7) << 4));
        *(ull*)(sWhi + off) = hp; *(ull*)(sWlo + off) = lp;
    }

    // ---- init biases + h0 seed ----
    const int gid = bid*NTHR + t, gs = NBLK*NTHR;
    for (int j = gid; j < H_; j += gs){ g_b0[j] = bih0[j] + bhh0[j]; g_b1[j] = bih1[j] + bhh1[j]; }
    for (int i = gid; i < BH; i += gs) g_h0[1][i] = h0_in[i];
    gbar(bid, phase, ep_base);

    // per-lane ldmatrix geometry (all NON-trans; B is N x K row-major = .col operand)
    const int r   = l & 7;
    const u32 r16 = (u32)r << 4;
    const int halfm = (l >> 3) & 1;      // A: m-half | B: k-half
    const int kh    = l >> 4;            // A: k-half | B: n-half
    const u32 aWhi = smaddr(sWhi), aWlo = smaddr(sWlo);
    const u32 aAhi = smaddr(sAhi), aAlo = smaddr(sAlo);
    u32 aOff[4], bOff[2];
    #pragma unroll
    for (int mt = 0; mt < 4; ++mt) aOff[mt] = (u32)(mt*16 + halfm*8 + r) * 256;
    #pragma unroll
    for (int nt2 = 0; nt2 < 2; ++nt2) bOff[nt2] = (u32)(w*32 + nt2*16 + kh*8 + r) * 256;
    const u32 aKl = (u32)kh << 4;        // A lane k-byte offset (k+8)
    const u32 bKl = (u32)halfm << 4;     // B lane k-byte offset (k+8)

    for (int s = 0; s <= T_; ++s){
        const float* h0p = g_h0[(s + 1) & 1];
        const bool act = (kind <= 1) ? (s < T_) : (s >= 1);

        if (act){
            const float* Asrc;
            if (kind == 0 || kind == 2) Asrc = h0p + k0;
            else if (kind == 1)         Asrc = input + (size_t)s*BH + k0;
            else                        Asrc = ((s == 1) ? (h0_in + BH) : (out + (size_t)(s-2)*BH)) + k0;

            // stage A hi/lo (64 rows x 128 k)
            for (int u = t; u < 64*32; u += NTHR){
                int rr = u >> 5, kq = u & 31;
                float4 v = *(const float4*)&Asrc[(size_t)rr*1024 + 4*kq];
                ull hp, lp; split4(v, hp, lp);
                int off = rr*256 + ((kq*8) ^ ((rr & 7) << 4));
                *(ull*)(sAhi + off) = hp; *(ull*)(sAlo + off) = lp;
            }
            __syncthreads();

            float acc[4][4][4];
            #pragma unroll
            for (int i = 0; i < 4; ++i)
                #pragma unroll
                for (int j = 0; j < 4; ++j)
                    #pragma unroll
                    for (int q = 0; q < 4; ++q) acc[i][j][q] = 0.f;

            #pragma unroll
            for (int pass = 0; pass < 3; ++pass){
                const u32 aB = (pass == 1) ? aAlo : aAhi;
                const u32 bB = (pass == 2) ? aWlo : aWhi;
                #pragma unroll
                for (int ks = 0; ks < 8; ++ks){
                    u32 a[4][4], b[2][4];
                    #pragma unroll
                    for (int mt = 0; mt < 4; ++mt)
                        ldsm4(a[mt][0], a[mt][1], a[mt][2], a[mt][3],
                              aB + aOff[mt] + (((u32)(ks*32) + aKl) ^ r16));
                    #pragma unroll
                    for (int nt2 = 0; nt2 < 2; ++nt2)
                        ldsm4(b[nt2][0], b[nt2][1], b[nt2][2], b[nt2][3],
                              bB + bOff[nt2] + (((u32)(ks*32) + bKl) ^ r16));
                    #pragma unroll
                    for (int mt = 0; mt < 4; ++mt)
                        #pragma unroll
                        for (int nt2 = 0; nt2 < 2; ++nt2){
                            mma16816(acc[mt][2*nt2],   a[mt][0],a[mt][1],a[mt][2],a[mt][3], b[nt2][0], b[nt2][1]);
                            mma16816(acc[mt][2*nt2+1], a[mt][0],a[mt][1],a[mt][2],a[mt][3], b[nt2][2], b[nt2][3]);
                        }
                }
            }

            // epilogue: d-frag -> partials (row-major, float2 stores)
            const int erow = l >> 2, ecol = (l & 3)*2;
            #pragma unroll
            for (int mt = 0; mt < 4; ++mt)
                #pragma unroll
                for (int nt = 0; nt < 4; ++nt){
                    const int row = mt*16 + erow;
                    const int col = j0 + w*32 + nt*8 + ecol;
                    *(float2*)&P[(size_t)row*1024 + col]      = make_float2(acc[mt][nt][0], acc[mt][nt][1]);
                    *(float2*)&P[(size_t)(row+8)*1024 + col]  = make_float2(acc[mt][nt][2], acc[mt][nt][3]);
                }
        }
        gbar(bid, phase, ep_base);

        // ---- reduce + tanh ----
        for (int i = gid; i < 2*(BH/4); i += gs){
            if (i < BH/4){
                if (s < T_){
                    float4 v = *(const float4*)&g_b0[(i & 255)*4];
                    #pragma unroll
                    for (int p = 0; p < 8; ++p){
                        float4 a = *(const float4*)&g_p0[p][i*4];
                        float4 b = *(const float4*)&g_px[p][i*4];
                        v.x += a.x + b.x; v.y += a.y + b.y;
                        v.z += a.z + b.z; v.w += a.w + b.w;
                    }
                    *(float4*)&g_h0[s & 1][i*4] =
                        make_float4(tanhf(v.x), tanhf(v.y), tanhf(v.z), tanhf(v.w));
                }
            } else if (s >= 1){
                int e = i - BH/4;
                float4 v = *(const float4*)&g_b1[(e & 255)*4];
                #pragma unroll
                for (int p = 0; p < 16; ++p){
                    float4 a = *(const float4*)&g_p1[p][e*4];
                    v.x += a.x; v.y += a.y; v.z += a.z; v.w += a.w;
                }
                *(float4*)&out[(size_t)(s-1)*BH + e*4] =
                    make_float4(tanhf(v.x), tanhf(v.y), tanhf(v.z), tanhf(v.w));
            }
        }
        gbar(bid, phase, ep_base);
    }

    for (int i = gid; i < BH; i += gs){
        out[TBH + i]      = g_h0[(T_ - 1) & 1][i];
        out[TBH + BH + i] = out[(size_t)(T_ - 1)*BH + i];
    }
}

extern "C" void kernel_launch(void* const* d_in, const int* in_sizes, int n_in,
                              void* d_out, int out_size)
{
    const float* input = (const float*)d_in[0];
    const float* h0in  = (const float*)d_in[1];
    const float* Wih0  = (const float*)d_in[2];
    const float* bih0  = (const float*)d_in[3];
    const float* Whh0  = (const float*)d_in[4];
    const float* bhh0  = (const float*)d_in[5];
    const float* Wih1  = (const float*)d_in[6];
    const float* bih1  = (const float*)d_in[7];
    const float* Whh1  = (const float*)d_in[8];
    const float* bhh1  = (const float*)d_in[9];
    float* out = (float*)d_out;

    cudaFuncSetAttribute(k_rnn, cudaFuncAttributeMaxDynamicSharedMemorySize, SMEM_BYTES);
    k_rnn<<<NBLK, NTHR, SMEM_BYTES>>>(input, h0in, Wih0, bih0, Whh0, bhh0,
                                      Wih1, bih1, Whh1, bhh1, out);
}